// round 17
// baseline (speedup 1.0000x reference)
#include <cuda_runtime.h>
#include <cuda_bf16.h>
#include <math.h>
#include <stdint.h>

#define QLEN   512
#define MLEN   512
#define KLEN   1024
#define RLEN   1536
#define BATCH  4
#define DMODEL 1024
#define NHEAD  16
#define DHEAD  64
#define BN_TOT (BATCH*NHEAD)
#define SCALE_F 0.125f
#define LN_EPS 1e-3f

// ---------------- scratch (device globals; no allocation allowed) ----------------
__device__ float g_q  [(size_t)QLEN*BATCH*DMODEL];     // tf32-rounded
__device__ float g_k  [(size_t)KLEN*BATCH*DMODEL];     // tf32-rounded
__device__ float g_v  [(size_t)KLEN*BATCH*DMODEL];     // tf32-rounded
__device__ float g_kr [(size_t)RLEN*BATCH*DMODEL];     // tf32-rounded
__device__ float g_e  [QLEN*BATCH*NHEAD*2];
__device__ float g_rwk [BN_TOT*KLEN];
__device__ float g_rrkr[BN_TOT*RLEN];
__device__ float g_ac [(size_t)BN_TOT*QLEN*KLEN];      // 128 MB
__device__ float g_bd [(size_t)BN_TOT*QLEN*RLEN];      // 192 MB
__device__ float g_scores[(size_t)BN_TOT*QLEN*KLEN];   // probs (tf32 bits), 128 MB
__device__ float g_att[(size_t)QLEN*BATCH*DMODEL];
__device__ unsigned char g_packed[(size_t)BATCH*QLEN*KLEN]; // 2 MB: bit0=seg_id, bit1=mask

// bf16-converted operands (packed 2 halves per word)
__device__ unsigned g_htb  [(size_t)QLEN*BATCH*DMODEL/2];
__device__ unsigned g_cattb[(size_t)KLEN*BATCH*DMODEL/2];
__device__ unsigned g_rtb  [(size_t)RLEN*BATCH*DMODEL/2];
__device__ unsigned g_wqb  [DMODEL*DMODEL/2];   // transposed [N,K]
__device__ unsigned g_wkb  [DMODEL*DMODEL/2];   // transposed
__device__ unsigned g_wvb  [DMODEL*DMODEL/2];   // transposed
__device__ unsigned g_wrb  [DMODEL*DMODEL/2];   // transposed
__device__ unsigned g_wob  [DMODEL*DMODEL/2];   // native [h, nd] == NT already
__device__ unsigned g_vecb [(size_t)QLEN*BATCH*DMODEL/2];

// ---------------- helpers ----------------
__device__ __forceinline__ unsigned f2tf(float f) {
    unsigned u;
    asm("cvt.rna.tf32.f32 %0, %1;" : "=r"(u) : "f"(f));
    return u;
}
__device__ __forceinline__ unsigned pack_bf16(float lo, float hi) {
    unsigned w;
    asm("cvt.rn.bf16x2.f32 %0, %1, %2;" : "=r"(w) : "f"(hi), "f"(lo));
    return w;
}
__device__ __forceinline__ void cp16(void* dst, const void* src) {
    unsigned d = (unsigned)__cvta_generic_to_shared(dst);
    asm volatile("cp.async.cg.shared.global [%0], [%1], 16;" :: "r"(d), "l"(src));
}
__device__ __forceinline__ void mma_tf32(float* c, const unsigned* a, const unsigned* b) {
    asm volatile("mma.sync.aligned.m16n8k8.row.col.f32.tf32.tf32.f32 "
                 "{%0,%1,%2,%3}, {%4,%5,%6,%7}, {%8,%9}, {%0,%1,%2,%3};"
                 : "+f"(c[0]), "+f"(c[1]), "+f"(c[2]), "+f"(c[3])
                 : "r"(a[0]), "r"(a[1]), "r"(a[2]), "r"(a[3]), "r"(b[0]), "r"(b[1]));
}
__device__ __forceinline__ void mma_bf16(float* c, const unsigned* a, const unsigned* b) {
    asm volatile("mma.sync.aligned.m16n8k16.row.col.f32.bf16.bf16.f32 "
                 "{%0,%1,%2,%3}, {%4,%5,%6,%7}, {%8,%9}, {%0,%1,%2,%3};"
                 : "+f"(c[0]), "+f"(c[1]), "+f"(c[2]), "+f"(c[3])
                 : "r"(a[0]), "r"(a[1]), "r"(a[2]), "r"(a[3]), "r"(b[0]), "r"(b[1]));
}

// fp32 -> packed bf16 (each thread: 4 floats -> 2 words)
__global__ __launch_bounds__(256) void cvt_bf16(const float* __restrict__ in,
                                                unsigned* __restrict__ out)
{
    int i = blockIdx.x*256 + threadIdx.x;
    float4 v = ((const float4*)in)[i];
    ((uint2*)out)[i] = make_uint2(pack_bf16(v.x, v.y), pack_bf16(v.z, v.w));
}

// fp32 [K=1024, N=1024] -> bf16 transposed [N, K]
__global__ __launch_bounds__(256) void cvt_bf16_T(const float* __restrict__ in,
                                                  __nv_bfloat16* __restrict__ out)
{
    __shared__ float t[32][33];
    const int k0 = blockIdx.y*32, n0 = blockIdx.x*32;
    const int tx = threadIdx.x & 31, ty = threadIdx.x >> 5;  // 8 rows per pass
    #pragma unroll
    for (int r = 0; r < 32; r += 8)
        t[ty+r][tx] = in[(size_t)(k0+ty+r)*DMODEL + n0+tx];
    __syncthreads();
    #pragma unroll
    for (int r = 0; r < 32; r += 8)
        out[(size_t)(n0+ty+r)*DMODEL + k0+tx] = __float2bfloat16(t[tx][ty+r]);
}

// ---------------- pack seg_mat + attn_mask into byte table ----------------
__global__ __launch_bounds__(256) void pack_kernel(const float* __restrict__ seg_mat,
                                                   const float* __restrict__ attn_mask)
{
    int idx = blockIdx.x*256 + threadIdx.x;          // 0 .. 512*1024-1
    int i = idx >> 10;
    int j = idx & (KLEN-1);
    float4 s01 = ((const float4*)seg_mat)[idx*2];
    float4 s23 = ((const float4*)seg_mat)[idx*2+1];
    float4 mk  = ((const float4*)attn_mask)[idx];
    unsigned char v0 = (s01.y > 0.5f ? 1 : 0) | (mk.x > 0.5f ? 2 : 0);
    unsigned char v1 = (s01.w > 0.5f ? 1 : 0) | (mk.y > 0.5f ? 2 : 0);
    unsigned char v2 = (s23.y > 0.5f ? 1 : 0) | (mk.z > 0.5f ? 2 : 0);
    unsigned char v3 = (s23.w > 0.5f ? 1 : 0) | (mk.w > 0.5f ? 2 : 0);
    g_packed[((size_t)0*QLEN + i)*KLEN + j] = v0;
    g_packed[((size_t)1*QLEN + i)*KLEN + j] = v1;
    g_packed[((size_t)2*QLEN + i)*KLEN + j] = v2;
    g_packed[((size_t)3*QLEN + i)*KLEN + j] = v3;
}

// ---------------- bf16 tensor-core GEMM, NT: C[M,1024] = A[M,1024] * B[1024,1024]^T ----------------
// A, B packed bf16 (2 halves/word): 512 words per row of 1024 halves.
#define KW  512
#define BFST 36   // smem row stride in words (32 data + 4 pad)

template<int RND>
__global__ __launch_bounds__(256, 2) void gemm_bf16(const unsigned* __restrict__ A,
                                                    const unsigned* __restrict__ B,
                                                    float* __restrict__ C, int M)
{
    constexpr int N = 1024;
    constexpr int TSZ = 128*BFST;
    constexpr int NIT = 16;                  // 16 iters x 64 k-halves
    extern __shared__ unsigned sm[];
    unsigned* sA[2] = { sm,        sm + 2*TSZ };
    unsigned* sB[2] = { sm + TSZ,  sm + 3*TSZ };

    const int tid = threadIdx.x;
    const int m0 = blockIdx.y << 7;
    const int n0 = blockIdx.x << 7;
    const int lane = tid & 31, wid = tid >> 5;
    const int wr = wid >> 2, wc = wid & 3;

    float acc[4][4][4] = {};

    auto issue = [&](int it, int st) {
        int k0 = it * 32;                    // word offset
        #pragma unroll
        for (int q = 0; q < 4; q++) {
            int idx = tid + 256*q;
            int row = idx >> 3, kc = (idx & 7) * 4;
            cp16(&sA[st][row*BFST + kc], &A[(size_t)(m0+row)*KW + k0 + kc]);
        }
        #pragma unroll
        for (int q = 0; q < 4; q++) {
            int idx = tid + 256*q;
            int row = idx >> 3, kc = (idx & 7) * 4;
            cp16(&sB[st][row*BFST + kc], &B[(size_t)(n0+row)*KW + k0 + kc]);
        }
        asm volatile("cp.async.commit_group;");
    };

    issue(0, 0);
    for (int it = 0; it < NIT; it++) {
        int st = it & 1;
        if (it + 1 < NIT) issue(it+1, st^1);
        if (it + 1 < NIT) asm volatile("cp.async.wait_group 1;");
        else              asm volatile("cp.async.wait_group 0;");
        __syncthreads();

        const unsigned* Ab = sA[st] + (wr*64 + (lane>>2))*BFST + (lane&3);
        #pragma unroll
        for (int ks = 0; ks < 4; ks++) {     // 4 x k16
            unsigned a[4][4];
            #pragma unroll
            for (int mt = 0; mt < 4; mt++) {
                const unsigned* p = Ab + mt*16*BFST + ks*8;
                a[mt][0] = p[0];
                a[mt][1] = p[8*BFST];
                a[mt][2] = p[4];
                a[mt][3] = p[8*BFST + 4];
            }
            unsigned b[4][2];
            #pragma unroll
            for (int nt = 0; nt < 4; nt++) {
                const unsigned* p = sB[st] + (wc*32 + nt*8 + (lane>>2))*BFST + ks*8 + (lane&3);
                b[nt][0] = p[0];
                b[nt][1] = p[4];
            }
            #pragma unroll
            for (int mt = 0; mt < 4; mt++)
                #pragma unroll
                for (int nt = 0; nt < 4; nt++)
                    mma_bf16(acc[mt][nt], a[mt], b[nt]);
        }
        __syncthreads();
    }

    #pragma unroll
    for (int mt = 0; mt < 4; mt++) {
        int row = m0 + wr*64 + mt*16 + (lane>>2);
        #pragma unroll
        for (int nt = 0; nt < 4; nt++) {
            int col = n0 + wc*32 + nt*8 + 2*(lane&3);
            float v0 = acc[mt][nt][0], v1 = acc[mt][nt][1];
            float v2 = acc[mt][nt][2], v3 = acc[mt][nt][3];
            if (RND) {
                v0 = __uint_as_float(f2tf(v0)); v1 = __uint_as_float(f2tf(v1));
                v2 = __uint_as_float(f2tf(v2)); v3 = __uint_as_float(f2tf(v3));
            }
            *(float2*)&C[(size_t)row*N + col]     = make_float2(v0, v1);
            *(float2*)&C[(size_t)(row+8)*N + col] = make_float2(v2, v3);
        }
    }
}

// ---------------- batched per-head GEMM (tf32): C[bn] = A_head @ B_head^T, K=64 ----------------
__global__ __launch_bounds__(256, 2) void head_gemm(const unsigned* __restrict__ A,
                                                    const unsigned* __restrict__ Bm,
                                                    float* __restrict__ C, int Ntot)
{
    extern __shared__ unsigned sm[];
    unsigned* sA = sm;             // 128 x 68
    unsigned* sB = sm + 128*68;    // 128 x 68
    const int bn = blockIdx.z, b = bn >> 4, n = bn & 15;
    const int i0 = blockIdx.y << 7, j0 = blockIdx.x << 7;
    const int tid = threadIdx.x, lane = tid & 31, wid = tid >> 5;
    const int wr = wid >> 2, wc = wid & 3;
    const size_t hoff = (size_t)b*DMODEL + n*DHEAD;

    #pragma unroll
    for (int q = 0; q < 8; q++) {
        int idx = tid + 256*q;
        int row = idx >> 4, kc = (idx & 15) * 4;
        cp16(&sA[row*68 + kc], &A[(size_t)(i0+row)*(BATCH*DMODEL) + hoff + kc]);
    }
    #pragma unroll
    for (int q = 0; q < 8; q++) {
        int idx = tid + 256*q;
        int row = idx >> 4, kc = (idx & 15) * 4;
        cp16(&sB[row*68 + kc], &Bm[(size_t)(j0+row)*(BATCH*DMODEL) + hoff + kc]);
    }
    asm volatile("cp.async.commit_group;\n\tcp.async.wait_group 0;");
    __syncthreads();

    float acc[4][4][4] = {};
    const unsigned* Ab = sA + (wr*64 + (lane>>2))*68 + (lane&3);
    #pragma unroll
    for (int ks = 0; ks < 8; ks++) {
        unsigned a[4][4];
        #pragma unroll
        for (int mt = 0; mt < 4; mt++) {
            const unsigned* p = Ab + mt*16*68 + ks*8;
            a[mt][0] = p[0];
            a[mt][1] = p[8*68];
            a[mt][2] = p[4];
            a[mt][3] = p[8*68 + 4];
        }
        unsigned bf[4][2];
        #pragma unroll
        for (int nt = 0; nt < 4; nt++) {
            const unsigned* p = sB + (wc*32 + nt*8 + (lane>>2))*68 + ks*8 + (lane&3);
            bf[nt][0] = p[0];
            bf[nt][1] = p[4];
        }
        #pragma unroll
        for (int mt = 0; mt < 4; mt++)
            #pragma unroll
            for (int nt = 0; nt < 4; nt++)
                mma_tf32(acc[mt][nt], a[mt], bf[nt]);
    }

    #pragma unroll
    for (int mt = 0; mt < 4; mt++) {
        int row = i0 + wr*64 + mt*16 + (lane>>2);
        #pragma unroll
        for (int nt = 0; nt < 4; nt++) {
            int col = j0 + wc*32 + nt*8 + 2*(lane&3);
            *(float2*)&C[((size_t)bn*QLEN + row)*Ntot + col] =
                make_float2(acc[mt][nt][0], acc[mt][nt][1]);
            *(float2*)&C[((size_t)bn*QLEN + row + 8)*Ntot + col] =
                make_float2(acc[mt][nt][2], acc[mt][nt][3]);
        }
    }
}

// ---------------- bias dot tables ----------------
__global__ void rwk_kernel(const float* __restrict__ rw)
{
    int idx = blockIdx.x*blockDim.x + threadIdx.x;
    int j = idx & (KLEN-1);
    int bn = idx >> 10;
    int b = bn >> 4, n = bn & 15;
    const float* krow = &g_k[((size_t)j*BATCH + b)*DMODEL + n*DHEAD];
    const float* w = &rw[n*DHEAD];
    float s = 0.f;
    #pragma unroll 16
    for (int d = 0; d < DHEAD; d++) s += w[d]*krow[d];
    g_rwk[idx] = s;
}

__global__ void rrkr_kernel(const float* __restrict__ rr)
{
    int idx = blockIdx.x*blockDim.x + threadIdx.x;
    int jr = idx % RLEN;
    int bn = idx / RLEN;
    int b = bn >> 4, n = bn & 15;
    const float* krow = &g_kr[((size_t)jr*BATCH + b)*DMODEL + n*DHEAD];
    const float* w = &rr[n*DHEAD];
    float s = 0.f;
    #pragma unroll 16
    for (int d = 0; d < DHEAD; d++) s += w[d]*krow[d];
    g_rrkr[idx] = s;
}

__global__ void e_kernel(const float* __restrict__ rs, const float* __restrict__ seg)
{
    int idx = blockIdx.x*blockDim.x + threadIdx.x;
    int n = idx & 15;
    int ib = idx >> 4;
    int b = ib & 3, i = ib >> 2;
    const float* q = &g_q[((size_t)i*BATCH + b)*DMODEL + n*DHEAD];
    const float* w = &rs[n*DHEAD];
    const float* s0p = &seg[(0*NHEAD + n)*DHEAD];
    const float* s1p = &seg[(1*NHEAD + n)*DHEAD];
    float s0 = 0.f, s1 = 0.f;
    #pragma unroll 16
    for (int d = 0; d < DHEAD; d++) {
        float qr = q[d] + w[d];
        s0 += qr*s0p[d];
        s1 += qr*s1p[d];
    }
    g_e[idx*2+0] = s0;
    g_e[idx*2+1] = s1;
}

// ---------------- fused score assembly + softmax; writes tf32 probs ----------------
__global__ __launch_bounds__(256) void score_softmax()
{
    __shared__ float red[8];
    __shared__ float bcast;
    const int i = blockIdx.x, bn = blockIdx.y;
    const int b = bn >> 4, n = bn & 15;
    const int tid = threadIdx.x;
    const size_t rowid = (size_t)bn*QLEN + i;
    const int shift = 512 - i;

    const float* ac   = &g_ac[rowid*KLEN];
    const float* bd   = &g_bd[rowid*RLEN + shift];
    const float* rwk  = &g_rwk[bn*KLEN];
    const float* rrkr = &g_rrkr[(size_t)bn*RLEN + shift];
    const float  e0s  = g_e[(((size_t)i*BATCH + b)*NHEAD + n)*2 + 0] * SCALE_F;
    const float  e1s  = g_e[(((size_t)i*BATCH + b)*NHEAD + n)*2 + 1] * SCALE_F;
    const unsigned char* pk = &g_packed[((size_t)b*QLEN + i)*KLEN];

    float4 acv  = ((const float4*)ac)[tid];
    float4 rwkv = ((const float4*)rwk)[tid];
    uchar4 pc   = ((const uchar4*)pk)[tid];
    const int j = tid * 4;
    float sc[4];
    {
        float a0 = acv.x + bd[j+0] + rwkv.x + rrkr[j+0];
        float a1 = acv.y + bd[j+1] + rwkv.y + rrkr[j+1];
        float a2 = acv.z + bd[j+2] + rwkv.z + rrkr[j+2];
        float a3 = acv.w + bd[j+3] + rwkv.w + rrkr[j+3];
        sc[0] = a0*SCALE_F + ((pc.x & 1) ? e1s : e0s) - ((pc.x & 2) ? 1e30f : 0.f);
        sc[1] = a1*SCALE_F + ((pc.y & 1) ? e1s : e0s) - ((pc.y & 2) ? 1e30f : 0.f);
        sc[2] = a2*SCALE_F + ((pc.z & 1) ? e1s : e0s) - ((pc.z & 2) ? 1e30f : 0.f);
        sc[3] = a3*SCALE_F + ((pc.w & 1) ? e1s : e0s) - ((pc.w & 2) ? 1e30f : 0.f);
    }

    float m = fmaxf(fmaxf(sc[0], sc[1]), fmaxf(sc[2], sc[3]));
    #pragma unroll
    for (int o = 16; o; o >>= 1) m = fmaxf(m, __shfl_xor_sync(0xffffffffu, m, o));
    if ((tid & 31) == 0) red[tid >> 5] = m;
    __syncthreads();
    if (tid < 32) {
        float t = (tid < 8) ? red[tid] : -INFINITY;
        #pragma unroll
        for (int o = 4; o; o >>= 1) t = fmaxf(t, __shfl_xor_sync(0xffffffffu, t, o));
        if (tid == 0) bcast = t;
    }
    __syncthreads();
    m = bcast;
    __syncthreads();

    float ssum = 0.f;
    #pragma unroll
    for (int u = 0; u < 4; u++) { sc[u] = __expf(sc[u] - m); ssum += sc[u]; }
    #pragma unroll
    for (int o = 16; o; o >>= 1) ssum += __shfl_xor_sync(0xffffffffu, ssum, o);
    if ((tid & 31) == 0) red[tid >> 5] = ssum;
    __syncthreads();
    if (tid < 32) {
        float t = (tid < 8) ? red[tid] : 0.f;
        #pragma unroll
        for (int o = 4; o; o >>= 1) t += __shfl_xor_sync(0xffffffffu, t, o);
        if (tid == 0) bcast = 1.0f / t;
    }
    __syncthreads();
    float inv = bcast;

    uint4 o4;
    o4.x = f2tf(sc[0]*inv); o4.y = f2tf(sc[1]*inv);
    o4.z = f2tf(sc[2]*inv); o4.w = f2tf(sc[3]*inv);
    ((uint4*)&g_scores[rowid*KLEN])[tid] = o4;
}

// ---------------- PV on tensor cores (tf32); epilogue emits packed bf16 ----------------
__global__ __launch_bounds__(256, 2) void pv_mma()
{
    extern __shared__ unsigned sm[];
    unsigned* sP[2] = { sm,            sm + 128*36 + 32*68 };
    unsigned* sV[2] = { sm + 128*36,   sm + 2*(128*36) + 32*68 };
    const int bn = blockIdx.y, b = bn >> 4, n = bn & 15;
    const int i0 = blockIdx.x << 7;
    const int tid = threadIdx.x, lane = tid & 31, wid = tid >> 5;
    const int wr = wid >> 1, wc = wid & 1;
    const unsigned* P = (const unsigned*)g_scores;
    const unsigned* V = (const unsigned*)g_v;

    auto issue = [&](int it, int st) {
        int k0 = it * 32;
        #pragma unroll
        for (int q = 0; q < 4; q++) {
            int idx = tid + 256*q;
            int row = idx >> 3, kc = (idx & 7) * 4;
            cp16(&sP[st][row*36 + kc], &P[((size_t)bn*QLEN + i0 + row)*KLEN + k0 + kc]);
        }
        #pragma unroll
        for (int q = 0; q < 2; q++) {
            int idx = tid + 256*q;
            int row = idx >> 4, c4 = (idx & 15) * 4;
            cp16(&sV[st][row*68 + c4], &V[(size_t)(k0+row)*(BATCH*DMODEL) + (size_t)b*DMODEL + n*DHEAD + c4]);
        }
        asm volatile("cp.async.commit_group;");
    };

    float acc[2][4][4] = {};
    issue(0, 0);
    for (int it = 0; it < 32; it++) {
        int st = it & 1;
        if (it + 1 < 32) issue(it+1, st^1);
        if (it + 1 < 32) asm volatile("cp.async.wait_group 1;");
        else             asm volatile("cp.async.wait_group 0;");
        __syncthreads();

        const unsigned* Ab = sP[st] + (wr*32 + (lane>>2))*36 + (lane&3);
        #pragma unroll
        for (int ks = 0; ks < 4; ks++) {
            unsigned a[2][4];
            #pragma unroll
            for (int mt = 0; mt < 2; mt++) {
                const unsigned* p = Ab + mt*16*36 + ks*8;
                a[mt][0] = p[0];
                a[mt][1] = p[8*36];
                a[mt][2] = p[4];
                a[mt][3] = p[8*36 + 4];
            }
            unsigned bf[4][2];
            #pragma unroll
            for (int nt = 0; nt < 4; nt++) {
                const unsigned* p = sV[st] + (ks*8 + (lane&3))*68 + wc*32 + nt*8 + (lane>>2);
                bf[nt][0] = p[0];
                bf[nt][1] = p[4*68];
            }
            #pragma unroll
            for (int mt = 0; mt < 2; mt++)
                #pragma unroll
                for (int nt = 0; nt < 4; nt++)
                    mma_tf32(acc[mt][nt], a[mt], bf[nt]);
        }
        __syncthreads();
    }

    #pragma unroll
    for (int mt = 0; mt < 2; mt++) {
        int row = i0 + wr*32 + mt*16 + (lane>>2);
        #pragma unroll
        for (int nt = 0; nt < 4; nt++) {
            int col = wc*32 + nt*8 + 2*(lane&3);
            size_t w0 = (((size_t)row*BATCH + b)*DMODEL + n*DHEAD + col) >> 1;
            size_t w1 = (((size_t)(row+8)*BATCH + b)*DMODEL + n*DHEAD + col) >> 1;
            g_vecb[w0] = pack_bf16(acc[mt][nt][0], acc[mt][nt][1]);
            g_vecb[w1] = pack_bf16(acc[mt][nt][2], acc[mt][nt][3]);
        }
    }
}

// ---------------- out = layer_norm(attn_out + h) ----------------
__global__ __launch_bounds__(256) void addln_kernel(const float* __restrict__ h,
                                                    const float* __restrict__ gamma,
                                                    const float* __restrict__ beta,
                                                    float* __restrict__ out)
{
    __shared__ float red[8];
    __shared__ float bc;
    const int row = blockIdx.x;
    const int tid = threadIdx.x;
    float4 x  = ((const float4*)&g_att[(size_t)row*DMODEL])[tid];
    float4 hh = ((const float4*)&h[(size_t)row*DMODEL])[tid];
    x.x += hh.x; x.y += hh.y; x.z += hh.z; x.w += hh.w;

    float s = x.x + x.y + x.z + x.w;
    #pragma unroll
    for (int o = 16; o; o >>= 1) s += __shfl_xor_sync(0xffffffffu, s, o);
    if ((tid & 31) == 0) red[tid >> 5] = s;
    __syncthreads();
    if (tid < 32) {
        float t = (tid < 8) ? red[tid] : 0.f;
        #pragma unroll
        for (int o = 4; o; o >>= 1) t += __shfl_xor_sync(0xffffffffu, t, o);
        if (tid == 0) bc = t * (1.0f/DMODEL);
    }
    __syncthreads();
    float mu = bc;
    __syncthreads();

    float dx0 = x.x - mu, dx1 = x.y - mu, dx2 = x.z - mu, dx3 = x.w - mu;
    float sq = dx0*dx0 + dx1*dx1 + dx2*dx2 + dx3*dx3;
    #pragma unroll
    for (int o = 16; o; o >>= 1) sq += __shfl_xor_sync(0xffffffffu, sq, o);
    if ((tid & 31) == 0) red[tid >> 5] = sq;
    __syncthreads();
    if (tid < 32) {
        float t = (tid < 8) ? red[tid] : 0.f;
        #pragma unroll
        for (int o = 4; o; o >>= 1) t += __shfl_xor_sync(0xffffffffu, t, o);
        if (tid == 0) bc = rsqrtf(t * (1.0f/DMODEL) + LN_EPS);
    }
    __syncthreads();
    float inv = bc;

    float4 g = ((const float4*)gamma)[tid];
    float4 bt = ((const float4*)beta)[tid];
    float4 o4;
    o4.x = dx0*inv*g.x + bt.x;
    o4.y = dx1*inv*g.y + bt.y;
    o4.z = dx2*inv*g.z + bt.z;
    o4.w = dx3*inv*g.w + bt.w;
    ((float4*)&out[(size_t)row*DMODEL])[tid] = o4;
}

// ---------------- launch ----------------
extern "C" void kernel_launch(void* const* d_in, const int* in_sizes, int n_in,
                              void* d_out, int out_size)
{
    (void)in_sizes; (void)n_in; (void)out_size;
    const float* rw        = (const float*)d_in[0];
    const float* rs        = (const float*)d_in[1];
    const float* rr        = (const float*)d_in[2];
    const float* seg_embed = (const float*)d_in[3];
    const float* h         = (const float*)d_in[4];
    const float* r         = (const float*)d_in[5];
    const float* mems      = (const float*)d_in[6];
    const float* seg_mat   = (const float*)d_in[7];
    const float* attn_mask = (const float*)d_in[8];
    const float* wq        = (const float*)d_in[9];
    const float* wk        = (const float*)d_in[10];
    const float* wv        = (const float*)d_in[11];
    const float* wr        = (const float*)d_in[12];
    const float* wo        = (const float*)d_in[13];
    const float* gamma     = (const float*)d_in[14];
    const float* beta      = (const float*)d_in[15];

    void *p_q, *p_k, *p_v, *p_kr, *p_att, *p_ac, *p_bd;
    void *p_htb, *p_cattb, *p_rtb, *p_wqb, *p_wkb, *p_wvb, *p_wrb, *p_wob, *p_vecb;
    cudaGetSymbolAddress(&p_q,    g_q);
    cudaGetSymbolAddress(&p_k,    g_k);
    cudaGetSymbolAddress(&p_v,    g_v);
    cudaGetSymbolAddress(&p_kr,   g_kr);
    cudaGetSymbolAddress(&p_att,  g_att);
    cudaGetSymbolAddress(&p_ac,   g_ac);
    cudaGetSymbolAddress(&p_bd,   g_bd);
    cudaGetSymbolAddress(&p_htb,  g_htb);
    cudaGetSymbolAddress(&p_cattb,g_cattb);
    cudaGetSymbolAddress(&p_rtb,  g_rtb);
    cudaGetSymbolAddress(&p_wqb,  g_wqb);
    cudaGetSymbolAddress(&p_wkb,  g_wkb);
    cudaGetSymbolAddress(&p_wvb,  g_wvb);
    cudaGetSymbolAddress(&p_wrb,  g_wrb);
    cudaGetSymbolAddress(&p_wob,  g_wob);
    cudaGetSymbolAddress(&p_vecb, g_vecb);

    const int HN = QLEN*BATCH*DMODEL;
    const int WN = DMODEL*DMODEL;
    const int SMEM_BF = 4*128*BFST*4;   // 2 stages x (A+B) tiles = 73728
    cudaFuncSetAttribute((const void*)gemm_bf16<1>, cudaFuncAttributeMaxDynamicSharedMemorySize, SMEM_BF);
    cudaFuncSetAttribute((const void*)gemm_bf16<0>, cudaFuncAttributeMaxDynamicSharedMemorySize, SMEM_BF);

    // --- ordered so the 6th launch is the Q projection GEMM (ncu -s 5 -c 1 captures it) ---
    cvt_bf16<<<HN/1024, 256>>>(h,    (unsigned*)p_htb);                                  // 1
    cvt_bf16<<<HN/1024, 256>>>(mems, (unsigned*)p_cattb);                                // 2
    cvt_bf16<<<HN/1024, 256>>>(h,    (unsigned*)p_cattb + (size_t)MLEN*BATCH*DMODEL/2);  // 3
    cvt_bf16<<<RLEN*BATCH*DMODEL/1024, 256>>>(r, (unsigned*)p_rtb);                      // 4
    cvt_bf16_T<<<dim3(32,32), 256>>>(wq, (__nv_bfloat16*)p_wqb);                         // 5
    gemm_bf16<1><<<dim3(8,16), 256, SMEM_BF>>>((unsigned*)p_htb, (unsigned*)p_wqb, (float*)p_q, QLEN*BATCH); // 6 <- profiled
    cvt_bf16_T<<<dim3(32,32), 256>>>(wk, (__nv_bfloat16*)p_wkb);
    cvt_bf16_T<<<dim3(32,32), 256>>>(wv, (__nv_bfloat16*)p_wvb);
    cvt_bf16_T<<<dim3(32,32), 256>>>(wr, (__nv_bfloat16*)p_wrb);
    cvt_bf16<<<WN/1024, 256>>>(wo, (unsigned*)p_wob);   // wo already [h, nd] = NT layout
    gemm_bf16<1><<<dim3(8,32), 256, SMEM_BF>>>((unsigned*)p_cattb, (unsigned*)p_wkb, (float*)p_k,  KLEN*BATCH);
    gemm_bf16<1><<<dim3(8,32), 256, SMEM_BF>>>((unsigned*)p_cattb, (unsigned*)p_wvb, (float*)p_v,  KLEN*BATCH);
    gemm_bf16<1><<<dim3(8,48), 256, SMEM_BF>>>((unsigned*)p_rtb,   (unsigned*)p_wrb, (float*)p_kr, RLEN*BATCH);

    // pack seg/mask table (independent of GEMMs)
    pack_kernel<<<QLEN*KLEN/256, 256>>>(seg_mat, attn_mask);

    // bias dot tables
    rwk_kernel<<<BN_TOT*KLEN/256, 256>>>(rw);
    rrkr_kernel<<<BN_TOT*RLEN/256, 256>>>(rr);
    e_kernel<<<QLEN*BATCH*NHEAD/256, 256>>>(rs, seg_embed);

    // AC = Q@K^T, BD = Q@Kr^T (batched per head, tf32 tensor cores)
    const int SMEM_HG = 2*128*68*4;  // 69632
    cudaFuncSetAttribute((const void*)head_gemm, cudaFuncAttributeMaxDynamicSharedMemorySize, SMEM_HG);
    head_gemm<<<dim3(8, 4, 64),  256, SMEM_HG>>>((unsigned*)p_q, (unsigned*)p_k,  (float*)p_ac, KLEN);
    head_gemm<<<dim3(12, 4, 64), 256, SMEM_HG>>>((unsigned*)p_q, (unsigned*)p_kr, (float*)p_bd, RLEN);

    // fused score assembly + softmax (packed table; writes tf32 probs)
    score_softmax<<<dim3(QLEN, BN_TOT), 256>>>();

    // attn_vec = P @ V (tf32 tensor cores, epilogue emits bf16)
    const int SMEM_PV = (2*128*36 + 2*32*68)*4;  // 54272
    cudaFuncSetAttribute((const void*)pv_mma, cudaFuncAttributeMaxDynamicSharedMemorySize, SMEM_PV);
    pv_mma<<<dim3(4, 64), 256, SMEM_PV>>>();

    // attn_out = vec @ wo^T (bf16)
    gemm_bf16<0><<<dim3(8,16), 256, SMEM_BF>>>((unsigned*)p_vecb, (unsigned*)p_wob, (float*)p_att, QLEN*BATCH);

    // layernorm(attn_out + h)
    addln_kernel<<<QLEN*BATCH, 256>>>(h, gamma, beta, (float*)d_out);
}